// round 15
// baseline (speedup 1.0000x reference)
#include <cuda_runtime.h>
#include <cstdint>
#include <math.h>

namespace {
constexpr int NV = 512;
constexpr int C  = 256;
constexpr int MT = 32;        // j-rows per tile
constexpr int LDA = 260;      // padded smem stride (floats)
constexpr int LDV = 260;
constexpr int NWARP = 8;
constexpr int THREADS = 256;

// smem layout (floats)
constexpr int SM_A   = 0;                  // [MT][LDA]
constexpr int SM_V   = SM_A + MT * LDA;    // [MT][LDV]
constexpr int SM_N   = SM_V + MT * LDV;    // [C]
constexpr int SM_BQ  = SM_N + C;           // [C]
constexpr int SM_BK  = SM_BQ + C;          // [C]
constexpr int SM_BV  = SM_BK + C;          // [C]
constexpr int SM_STG = SM_BV + C;          // [32][9]
constexpr int SM_SC  = SM_STG + 32 * 9;    // [32]
constexpr int SM_P   = SM_SC + 32;         // [32]
constexpr int SM_SX  = SM_P + 32;          // [C] x accumulators (smem-resident)
constexpr int SM_RED = SM_SX + C;          // [NWARP]
constexpr int SMEM_FLOATS = SM_RED + NWARP;
constexpr int SMEM_BYTES  = SMEM_FLOATS * 4;   // ~73.1 KB -> 2 CTAs/SM
}

// Blocked tf32 weights: [mat][n_blk(32)][k_blk(32)][64], 8x8 tile contiguous,
// pair-permuted so lane (qid,qlane) reads its B fragment as one float2.
__device__ float g_wt[3 * C * C];

__device__ __forceinline__ float to_tf32(float x) {
    float y; asm("cvt.rna.tf32.f32 %0, %1;" : "=f"(y) : "f"(x)); return y;
}
__device__ __forceinline__ uint32_t smem_u32(const void* p) {
    uint32_t a;
    asm("{ .reg .u64 t; cvta.to.shared.u64 t, %1; cvt.u32.u64 %0, t; }" : "=r"(a) : "l"(p));
    return a;
}

__global__ __launch_bounds__(256) void prep_weights(
    const float* __restrict__ Wq, const float* __restrict__ Wk, const float* __restrict__ Wv)
{
    const int id  = blockIdx.x * 256 + threadIdx.x;
    const int row = id >> 5, blk = id & 31;
    const float* src = (blockIdx.y == 0) ? Wq : (blockIdx.y == 1 ? Wk : Wv);
    const float* p = src + (size_t)row * C + blk * 8;
    float4 lo = *reinterpret_cast<const float4*>(p);
    float4 hi = *reinterpret_cast<const float4*>(p + 4);
    float4 o0, o1;   // pair-permuted
    o0.x = to_tf32(lo.x); o0.y = to_tf32(hi.x); o0.z = to_tf32(lo.y); o0.w = to_tf32(hi.y);
    o1.x = to_tf32(lo.z); o1.y = to_tf32(hi.z); o1.z = to_tf32(lo.w); o1.w = to_tf32(hi.w);
    float* dst = g_wt + (size_t)blockIdx.y * C * C
               + ((size_t)(row >> 3) * 32 + blk) * 64 + (row & 7) * 8;
    *reinterpret_cast<float4*>(dst)     = o0;
    *reinterpret_cast<float4*>(dst + 4) = o1;
}

__device__ __forceinline__ void mma8(float c[4], const uint32_t a[4], const uint32_t* b) {
    asm volatile(
        "mma.sync.aligned.m16n8k8.row.col.f32.tf32.tf32.f32 "
        "{%0,%1,%2,%3}, {%4,%5,%6,%7}, {%8,%9}, {%0,%1,%2,%3};"
        : "+f"(c[0]), "+f"(c[1]), "+f"(c[2]), "+f"(c[3])
        : "r"(a[0]), "r"(a[1]), "r"(a[2]), "r"(a[3]), "r"(b[0]), "r"(b[1]));
}

__device__ __forceinline__ void ldsm_x4(uint32_t a[4], uint32_t addr) {
    asm volatile("ldmatrix.sync.aligned.m8n8.x4.shared.b16 {%0,%1,%2,%3}, [%4];"
                 : "=r"(a[0]), "=r"(a[1]), "=r"(a[2]), "=r"(a[3]) : "r"(addr));
}

__device__ __forceinline__ void load_b2(uint32_t* b, const float* __restrict__ p, int kc) {
    const float2 t = *reinterpret_cast<const float2*>(p + kc * 64);
    b[0] = __float_as_uint(t.x);
    b[1] = __float_as_uint(t.y);
}

__global__ __launch_bounds__(THREADS, 2) void fused_kernel(
    const float* __restrict__ nmat, const float* __restrict__ s, const float* __restrict__ v,
    const float* __restrict__ bq, const float* __restrict__ bk, const float* __restrict__ bv,
    float* __restrict__ out)
{
    extern __shared__ float sm[];
    float* sA  = sm + SM_A;
    float* sv  = sm + SM_V;
    float* sn  = sm + SM_N;
    float* sbq = sm + SM_BQ;
    float* sbk = sm + SM_BK;
    float* sbv = sm + SM_BV;
    float* stg = sm + SM_STG;
    float* ssc = sm + SM_SC;
    float* sp  = sm + SM_P;
    float* sx  = sm + SM_SX;
    float* red = sm + SM_RED;

    const int i     = blockIdx.x;
    const int tid   = threadIdx.x;   // == channel (THREADS == C)
    const int wid   = tid >> 5;
    const int lane  = tid & 31;
    const int qid   = lane >> 2;
    const int qlane = lane & 3;
    const int wc0   = wid * 32;      // warp's first output column (4 n-blocks)

    const uint32_t aBase = smem_u32(sA)
        + (uint32_t)(((lane & 15) * LDA + ((lane >> 4) << 2)) * 4);

    // blocked-weight lane pointers (n_blk base = wid*4)
    const int boff = qid * 8 + qlane * 2;
    const float* pq = g_wt + (size_t)(wid * 4) * 2048 + boff;
    const float* pk = pq + 1 * C * C;
    const float* pv = pq + 2 * C * C;

    sn[tid]  = nmat[(size_t)i * C + tid];
    sbq[tid] = bq[tid];
    sbk[tid] = bk[tid];
    sbv[tid] = bv[tid];
    sx[tid]  = 0.0f;

    float m_run = -1e30f, l_run = 0.0f;

    for (int jt = 0; jt < NV / MT; jt++) {
        const int j0 = jt * MT;
        __syncthreads();   // prior-tile smem readers done (covers init on jt=0)

        // build A[j][c] = tf32(n_i[c]*n_j[c]*s[..]) and v-tile
#pragma unroll
        for (int it = 0; it < MT * (C / 4) / THREADS; it++) {
            const int idx = it * THREADS + tid;
            const int j  = idx >> 6;
            const int c4 = (idx & 63) * 4;
            const float4 n4  = *reinterpret_cast<const float4*>(nmat + (size_t)(j0 + j) * C + c4);
            const float4 s4  = *reinterpret_cast<const float4*>(s + ((size_t)i * NV + j0 + j) * C + c4);
            const float4 sn4 = *reinterpret_cast<const float4*>(sn + c4);
            float4 r;
            r.x = to_tf32(sn4.x * n4.x * s4.x);
            r.y = to_tf32(sn4.y * n4.y * s4.y);
            r.z = to_tf32(sn4.z * n4.z * s4.z);
            r.w = to_tf32(sn4.w * n4.w * s4.w);
            *reinterpret_cast<float4*>(sA + j * LDA + c4) = r;
            const float4 v4 = *reinterpret_cast<const float4*>(v + ((size_t)i * NV + j0 + j) * C + c4);
            *reinterpret_cast<float4*>(sv + j * LDV + c4) = v4;
        }
        __syncthreads();

        // ── single-pass fused Q+K+V GEMM
        float qacc[2][4][4], kacc[2][4][4], vacc[2][4][4];
#pragma unroll
        for (int mb = 0; mb < 2; mb++)
#pragma unroll
            for (int nb = 0; nb < 4; nb++)
#pragma unroll
                for (int e = 0; e < 4; e++) {
                    qacc[mb][nb][e] = 0.f; kacc[mb][nb][e] = 0.f; vacc[mb][nb][e] = 0.f;
                }
        {
#pragma unroll 2
            for (int kc = 0; kc < 32; kc++) {
                uint32_t a0[4], a1[4];
                ldsm_x4(a0, aBase + (uint32_t)((kc * 8) * 4));
                ldsm_x4(a1, aBase + (uint32_t)((16 * LDA + kc * 8) * 4));
                uint32_t bb[2][6];   // double-buffered over nb: 12 live b-regs
                load_b2(bb[0] + 0, pq, kc);
                load_b2(bb[0] + 2, pk, kc);
                load_b2(bb[0] + 4, pv, kc);
#pragma unroll
                for (int nb = 0; nb < 4; nb++) {
                    const int cur = nb & 1;
                    if (nb < 3) {
                        load_b2(bb[cur ^ 1] + 0, pq + (nb + 1) * 2048, kc);
                        load_b2(bb[cur ^ 1] + 2, pk + (nb + 1) * 2048, kc);
                        load_b2(bb[cur ^ 1] + 4, pv + (nb + 1) * 2048, kc);
                    }
                    mma8(qacc[0][nb], a0, bb[cur] + 0);
                    mma8(qacc[1][nb], a1, bb[cur] + 0);
                    mma8(kacc[0][nb], a0, bb[cur] + 2);
                    mma8(kacc[1][nb], a1, bb[cur] + 2);
                    mma8(vacc[0][nb], a0, bb[cur] + 4);
                    mma8(vacc[1][nb], a1, bb[cur] + 4);
                }
            }
        }

        // ── scores in-register
        {
            float pr[4] = {0.f, 0.f, 0.f, 0.f};
#pragma unroll
            for (int nb = 0; nb < 4; nb++) {
                const int c0 = wc0 + nb * 8 + 2 * qlane;
                const float bq0 = sbq[c0], bq1 = sbq[c0 + 1];
                const float bk0 = sbk[c0], bk1 = sbk[c0 + 1];
#pragma unroll
                for (int mb = 0; mb < 2; mb++) {
                    const int r0 = mb * 16 + qid;
                    const float2 va = *reinterpret_cast<const float2*>(sv + r0 * LDV + c0);
                    const float2 vb = *reinterpret_cast<const float2*>(sv + (r0 + 8) * LDV + c0);
                    pr[mb * 2 + 0] += (qacc[mb][nb][0] + bq0) * (kacc[mb][nb][0] + bk0) * va.x * va.x
                                    + (qacc[mb][nb][1] + bq1) * (kacc[mb][nb][1] + bk1) * va.y * va.y;
                    pr[mb * 2 + 1] += (qacc[mb][nb][2] + bq0) * (kacc[mb][nb][2] + bk0) * vb.x * vb.x
                                    + (qacc[mb][nb][3] + bq1) * (kacc[mb][nb][3] + bk1) * vb.y * vb.y;
                }
            }
#pragma unroll
            for (int z = 0; z < 4; z++) {
                pr[z] += __shfl_xor_sync(0xffffffffu, pr[z], 1);
                pr[z] += __shfl_xor_sync(0xffffffffu, pr[z], 2);
            }
            if (qlane == 0) {
                stg[(qid)      * 9 + wid] = pr[0];
                stg[(qid + 8)  * 9 + wid] = pr[1];
                stg[(qid + 16) * 9 + wid] = pr[2];
                stg[(qid + 24) * 9 + wid] = pr[3];
            }
        }
        __syncthreads();

        // row-reduce 8 warp partials -> scores (32 rows x 8 lanes = 256 threads)
        {
            const int row = tid >> 3, w8 = tid & 7;
            float ssum = stg[row * 9 + w8];
            ssum += __shfl_xor_sync(0xffffffffu, ssum, 1);
            ssum += __shfl_xor_sync(0xffffffffu, ssum, 2);
            ssum += __shfl_xor_sync(0xffffffffu, ssum, 4);
            if (w8 == 0) ssc[row] = ssum * 0.0625f;   // 1/sqrt(256)
        }
        __syncthreads();

        // online softmax (replicated) + rescale smem x-accumulators
        {
            float tm = -1e30f;
#pragma unroll 8
            for (int j = 0; j < MT; j++) tm = fmaxf(tm, ssc[j]);
            const float m_new = fmaxf(m_run, tm);
            const float scl = __expf(m_run - m_new);
            l_run *= scl;
            sx[tid] *= scl;
            if (tid < MT) sp[tid] = __expf(ssc[tid] - m_new);
            __syncthreads();
            float ls = 0.0f;
#pragma unroll 8
            for (int j = 0; j < MT; j++) ls += sp[j];
            l_run += ls;
            m_run = m_new;
        }

        // ── V epilogue straight from vacc -> sx
        {
#pragma unroll
            for (int nb = 0; nb < 4; nb++) {
                const int c0 = wc0 + nb * 8 + 2 * qlane;
                const float bv0 = sbv[c0], bv1 = sbv[c0 + 1];
                float pc0 = 0.f, pc1 = 0.f;
#pragma unroll
                for (int mb = 0; mb < 2; mb++) {
                    const int r0 = mb * 16 + qid;
                    const float p0 = sp[r0], p1 = sp[r0 + 8];
                    const float2 va = *reinterpret_cast<const float2*>(sv + r0 * LDV + c0);
                    const float2 vb = *reinterpret_cast<const float2*>(sv + (r0 + 8) * LDV + c0);
                    pc0 += p0 * (vacc[mb][nb][0] + bv0) * va.x
                         + p1 * (vacc[mb][nb][2] + bv0) * vb.x;
                    pc1 += p0 * (vacc[mb][nb][1] + bv1) * va.y
                         + p1 * (vacc[mb][nb][3] + bv1) * vb.y;
                }
                pc0 += __shfl_xor_sync(0xffffffffu, pc0, 4);
                pc0 += __shfl_xor_sync(0xffffffffu, pc0, 8);
                pc0 += __shfl_xor_sync(0xffffffffu, pc0, 16);
                pc1 += __shfl_xor_sync(0xffffffffu, pc1, 4);
                pc1 += __shfl_xor_sync(0xffffffffu, pc1, 8);
                pc1 += __shfl_xor_sync(0xffffffffu, pc1, 16);
                if (qid == 0) {
                    sx[c0]     += pc0;   // each col has exactly one writer lane
                    sx[c0 + 1] += pc1;
                }
            }
        }
    }

    // residual + L2 normalize (THREADS == C, one channel per thread)
    __syncthreads();
    const float x = sx[tid] / l_run + sn[tid];
    float sq = x * x;
#pragma unroll
    for (int o = 16; o > 0; o >>= 1) sq += __shfl_xor_sync(0xffffffffu, sq, o);
    if (lane == 0) red[wid] = sq;
    __syncthreads();
    float tot = 0.0f;
#pragma unroll
    for (int w = 0; w < NWARP; w++) tot += red[w];
    out[(size_t)i * C + tid] = x * rsqrtf(tot);
}

extern "C" void kernel_launch(void* const* d_in, const int* in_sizes, int n_in,
                              void* d_out, int out_size) {
    const float* nmat = (const float*)d_in[0];
    const float* s    = (const float*)d_in[1];
    const float* v    = (const float*)d_in[2];
    const float* Wq   = (const float*)d_in[3];
    const float* bq   = (const float*)d_in[4];
    const float* Wk   = (const float*)d_in[5];
    const float* bk   = (const float*)d_in[6];
    const float* Wv   = (const float*)d_in[7];
    const float* bv   = (const float*)d_in[8];

    prep_weights<<<dim3(32, 3), 256>>>(Wq, Wk, Wv);

    cudaFuncSetAttribute(fused_kernel, cudaFuncAttributeMaxDynamicSharedMemorySize, SMEM_BYTES);
    fused_kernel<<<NV, THREADS, SMEM_BYTES>>>(nmat, s, v, bq, bk, bv, (float*)d_out);
}